// round 17
// baseline (speedup 1.0000x reference)
#include <cuda_runtime.h>
#include <cuda_bf16.h>
#include <cstdint>
#include <math.h>

#define Bv 4
#define Sv 2048
#define Ev 1024
#define Hv 16
#define Dv 64
#define BSEn (Bv*Sv*Ev)

// pre-split hi/lo planes of raw inputs and weights
__device__ __nv_bfloat16 g_xqh[BSEn], g_xql[BSEn], g_xkh[BSEn], g_xkl[BSEn], g_xvh[BSEn], g_xvl[BSEn];
__device__ __nv_bfloat16 g_wqh[Ev*Ev], g_wql[Ev*Ev], g_wkh[Ev*Ev], g_wkl[Ev*Ev];
__device__ __nv_bfloat16 g_wvh[Ev*Ev], g_wvl[Ev*Ev], g_woh[Ev*Ev], g_wol[Ev*Ev];
// projected Q,K,V planes (GEMM epilogue) and attention-output planes (attn epilogue)
__device__ __nv_bfloat16 g_Qbh[BSEn], g_Qbl[BSEn];
__device__ __nv_bfloat16 g_Kbh[BSEn], g_Kbl[BSEn];
__device__ __nv_bfloat16 g_Vbh[BSEn], g_Vbl[BSEn];
__device__ __nv_bfloat16 g_Obh[BSEn], g_Obl[BSEn];

// ───────────── PTX helpers (base compute_103-legal) ─────────────
#define MMA_BF16(d, a0,a1,a2,a3, b0,b1) \
    asm volatile("mma.sync.aligned.m16n8k16.row.col.f32.bf16.bf16.f32 " \
        "{%0,%1,%2,%3}, {%4,%5,%6,%7}, {%8,%9}, {%0,%1,%2,%3};" \
        : "+f"((d)[0]), "+f"((d)[1]), "+f"((d)[2]), "+f"((d)[3]) \
        : "r"(a0), "r"(a1), "r"(a2), "r"(a3), "r"(b0), "r"(b1))

#define LDSM_X4(r0,r1,r2,r3, addr) \
    asm volatile("ldmatrix.sync.aligned.m8n8.x4.shared.b16 {%0,%1,%2,%3}, [%4];" \
        : "=r"(r0), "=r"(r1), "=r"(r2), "=r"(r3) : "r"(addr))

#define LDSM_X4_T(r0,r1,r2,r3, addr) \
    asm volatile("ldmatrix.sync.aligned.m8n8.x4.trans.shared.b16 {%0,%1,%2,%3}, [%4];" \
        : "=r"(r0), "=r"(r1), "=r"(r2), "=r"(r3) : "r"(addr))

#define CP_A16(dst, src) \
    asm volatile("cp.async.cg.shared.global [%0], [%1], 16;" :: "r"(dst), "l"(src))
#define CP_COMMIT() asm volatile("cp.async.commit_group;" ::: "memory")
#define CP_WAIT2()  asm volatile("cp.async.wait_group 2;" ::: "memory")
#define CP_WAIT1()  asm volatile("cp.async.wait_group 1;" ::: "memory")
#define CP_WAIT0()  asm volatile("cp.async.wait_group 0;" ::: "memory")

__device__ __forceinline__ uint32_t smem_u32(const void* p) {
    uint32_t a;
    asm("{ .reg .u64 t; cvta.to.shared.u64 t, %1; cvt.u32.u64 %0, t; }" : "=r"(a) : "l"(p));
    return a;
}

// pack 2 fp32 -> bf16x2 hi word (x lower, y upper), residual lo word
__device__ __forceinline__ uint32_t pack2f(float x, float y, uint32_t& lo) {
    uint32_t hi;
    asm("cvt.rn.bf16x2.f32 %0, %1, %2;" : "=r"(hi) : "f"(y), "f"(x));
    float fx = __uint_as_float(hi << 16);
    float fy = __uint_as_float(hi & 0xFFFF0000u);
    asm("cvt.rn.bf16x2.f32 %0, %1, %2;" : "=r"(lo) : "f"(y - fy), "f"(x - fx));
    return hi;
}

// ───────── fused elementwise fp32 -> hi/lo planes (z selects tensor) ─────────
__global__ __launch_bounds__(256)
void conv_in(const float* __restrict__ X0, const float* __restrict__ X1, const float* __restrict__ X2)
{
    const int z = blockIdx.y;
    const float* X = z == 0 ? X0 : z == 1 ? X1 : X2;
    __nv_bfloat16* Xh = z == 0 ? g_xqh : z == 1 ? g_xkh : g_xvh;
    __nv_bfloat16* Xl = z == 0 ? g_xql : z == 1 ? g_xkl : g_xvl;
    int i = blockIdx.x * 256 + threadIdx.x;
    float4 v = ((const float4*)X)[i];
    uint32_t lo0, lo1;
    uint32_t hi0 = pack2f(v.x, v.y, lo0);
    uint32_t hi1 = pack2f(v.z, v.w, lo1);
    ((uint2*)Xh)[i] = make_uint2(hi0, hi1);
    ((uint2*)Xl)[i] = make_uint2(lo0, lo1);
}

__global__ __launch_bounds__(256)
void conv_w(const float* __restrict__ W0, const float* __restrict__ W1,
            const float* __restrict__ W2, const float* __restrict__ W3)
{
    const int z = blockIdx.y;
    const float* X = z == 0 ? W0 : z == 1 ? W1 : z == 2 ? W2 : W3;
    __nv_bfloat16* Xh = z == 0 ? g_wqh : z == 1 ? g_wkh : z == 2 ? g_wvh : g_woh;
    __nv_bfloat16* Xl = z == 0 ? g_wql : z == 1 ? g_wkl : z == 2 ? g_wvl : g_wol;
    int i = blockIdx.x * 256 + threadIdx.x;
    float4 v = ((const float4*)X)[i];
    uint32_t lo0, lo1;
    uint32_t hi0 = pack2f(v.x, v.y, lo0);
    uint32_t hi1 = pack2f(v.z, v.w, lo1);
    ((uint2*)Xh)[i] = make_uint2(hi0, hi1);
    ((uint2*)Xl)[i] = make_uint2(lo0, lo1);
}

// ───────── GEMM on pre-split planes, cp.async double-buffered ─────────
#define G_STAGE 40960
#define G_SMEM  (2 * G_STAGE)

__device__ __forceinline__ void gemm_fill(uint32_t dstb,
    const __nv_bfloat16* __restrict__ AhG, const __nv_bfloat16* __restrict__ AlG,
    const __nv_bfloat16* __restrict__ WhG, const __nv_bfloat16* __restrict__ WlG,
    int brow, int bcol, int k0, int tid)
{
    const int r = tid >> 2, u = tid & 3;
    const uint32_t du = (uint32_t)(u * 16);
    const size_t so = (size_t)k0 + u * 8;
    CP_A16(dstb +     0u + (uint32_t)(r * 80)        + du, AhG + (size_t)(brow + r)      * 1024 + so);
    CP_A16(dstb +     0u + (uint32_t)((r + 64) * 80) + du, AhG + (size_t)(brow + r + 64) * 1024 + so);
    CP_A16(dstb + 10240u + (uint32_t)(r * 80)        + du, AlG + (size_t)(brow + r)      * 1024 + so);
    CP_A16(dstb + 10240u + (uint32_t)((r + 64) * 80) + du, AlG + (size_t)(brow + r + 64) * 1024 + so);
    CP_A16(dstb + 20480u + (uint32_t)(r * 80)        + du, WhG + (size_t)(bcol + r)      * 1024 + so);
    CP_A16(dstb + 20480u + (uint32_t)((r + 64) * 80) + du, WhG + (size_t)(bcol + r + 64) * 1024 + so);
    CP_A16(dstb + 30720u + (uint32_t)(r * 80)        + du, WlG + (size_t)(bcol + r)      * 1024 + so);
    CP_A16(dstb + 30720u + (uint32_t)((r + 64) * 80) + du, WlG + (size_t)(bcol + r + 64) * 1024 + so);
}

__device__ __forceinline__ void gemm_body(
    const __nv_bfloat16* AhG, const __nv_bfloat16* AlG,
    const __nv_bfloat16* WhG, const __nv_bfloat16* WlG,
    const float* bias, float* C, __nv_bfloat16* Chi, __nv_bfloat16* Clo,
    uint32_t smb, int brow, int bcol)
{
    const int tid = threadIdx.x;
    const int wid = tid >> 5;
    const int l   = tid & 31;
    const int wm = (wid & 1) * 64;
    const int wn = (wid >> 1) * 32;

    const int g   = l >> 3;
    const int rIn = l & 7;
    const uint32_t laneA_off = (uint32_t)(((g & 1) * 8 + rIn) * 80 + (g >> 1) * 16);
    const uint32_t laneW_off = (g < 2 ? 20480u : 30720u) + (uint32_t)(rIn * 80 + (g & 1) * 16);

    float acc[4][4][4] = {};

    gemm_fill(smb, AhG, AlG, WhG, WlG, brow, bcol, 0, tid);
    CP_COMMIT();

    for (int s = 0; s < 32; ++s) {
        const int p = s & 1;
        if (s + 1 < 32) {
            gemm_fill(smb + (uint32_t)((1 - p) * G_STAGE), AhG, AlG, WhG, WlG,
                      brow, bcol, (s + 1) * 32, tid);
            CP_COMMIT();
            CP_WAIT1();
        } else {
            CP_WAIT0();
        }
        __syncthreads();

        const uint32_t bb = smb + (uint32_t)(p * G_STAGE);
        #pragma unroll
        for (int ks = 0; ks < 2; ++ks) {
            uint32_t ah[4][4], al_[4][4];
            #pragma unroll
            for (int mt = 0; mt < 4; ++mt) {
                uint32_t off = (uint32_t)((wm + mt * 16) * 80 + ks * 32);
                LDSM_X4(ah[mt][0],  ah[mt][1],  ah[mt][2],  ah[mt][3],  bb + laneA_off + off);
                LDSM_X4(al_[mt][0], al_[mt][1], al_[mt][2], al_[mt][3], bb + 10240u + laneA_off + off);
            }
            #pragma unroll
            for (int nt = 0; nt < 4; ++nt) {
                uint32_t bh0, bh1, bl0, bl1;
                LDSM_X4(bh0, bh1, bl0, bl1, bb + laneW_off + (uint32_t)((wn + nt * 8) * 80 + ks * 32));
                #pragma unroll
                for (int mt = 0; mt < 4; ++mt) {
                    MMA_BF16(acc[mt][nt], ah[mt][0], ah[mt][1], ah[mt][2], ah[mt][3], bh0, bh1);
                    MMA_BF16(acc[mt][nt], ah[mt][0], ah[mt][1], ah[mt][2], ah[mt][3], bl0, bl1);
                    MMA_BF16(acc[mt][nt], al_[mt][0], al_[mt][1], al_[mt][2], al_[mt][3], bh0, bh1);
                }
            }
        }
        __syncthreads();
    }

    #pragma unroll
    for (int mt = 0; mt < 4; ++mt) {
        #pragma unroll
        for (int nt = 0; nt < 4; ++nt) {
            int gr = brow + wm + mt * 16 + (l >> 2);
            int gc = bcol + wn + nt * 8 + (l & 3) * 2;
            float2 b2 = make_float2(bias[gc], bias[gc + 1]);
            float v00 = acc[mt][nt][0] + b2.x, v01 = acc[mt][nt][1] + b2.y;
            float v10 = acc[mt][nt][2] + b2.x, v11 = acc[mt][nt][3] + b2.y;
            if (Chi) {
                uint32_t lo0, lo1;
                uint32_t hi0 = pack2f(v00, v01, lo0);
                uint32_t hi1 = pack2f(v10, v11, lo1);
                *(uint32_t*)&Chi[(size_t)gr * 1024 + gc]       = hi0;
                *(uint32_t*)&Clo[(size_t)gr * 1024 + gc]       = lo0;
                *(uint32_t*)&Chi[(size_t)(gr + 8) * 1024 + gc] = hi1;
                *(uint32_t*)&Clo[(size_t)(gr + 8) * 1024 + gc] = lo1;
            } else {
                *(float2*)(C + (size_t)gr * 1024 + gc)       = make_float2(v00, v01);
                *(float2*)(C + (size_t)(gr + 8) * 1024 + gc) = make_float2(v10, v11);
            }
        }
    }
}

__global__ __launch_bounds__(256, 2)
void gemm_qkv(const float* __restrict__ bq, const float* __restrict__ bk,
              const float* __restrict__ bv)
{
    extern __shared__ char gsm[];
    const int z = blockIdx.z;
    const __nv_bfloat16* AhG = z == 0 ? g_xqh : z == 1 ? g_xkh : g_xvh;
    const __nv_bfloat16* AlG = z == 0 ? g_xql : z == 1 ? g_xkl : g_xvl;
    const __nv_bfloat16* WhG = z == 0 ? g_wqh : z == 1 ? g_wkh : g_wvh;
    const __nv_bfloat16* WlG = z == 0 ? g_wql : z == 1 ? g_wkl : g_wvl;
    const float* bias        = z == 0 ? bq    : z == 1 ? bk    : bv;
    __nv_bfloat16* Chi       = z == 0 ? g_Qbh : z == 1 ? g_Kbh : g_Vbh;
    __nv_bfloat16* Clo       = z == 0 ? g_Qbl : z == 1 ? g_Kbl : g_Vbl;
    gemm_body(AhG, AlG, WhG, WlG, bias, (float*)0, Chi, Clo,
              smem_u32(gsm), blockIdx.y * 128, blockIdx.x * 128);
}

__global__ __launch_bounds__(256, 2)
void gemm_o(const float* __restrict__ bo, float* __restrict__ C)
{
    extern __shared__ char gsm[];
    gemm_body(g_Obh, g_Obl, g_woh, g_wol, bo, C, (__nv_bfloat16*)0, (__nv_bfloat16*)0,
              smem_u32(gsm), blockIdx.y * 128, blockIdx.x * 128);
}

// ─────── fused attention: phase A (S+PV+rowsum+O) then phase B (normalized P write) ───────
// smem: Qh 0, Ql 18432 | stage area 36864..110592
//   phase A: 2 stages of 36864 {Kh 0, Kl 9216, Vh 18432, Vl 27648}
//   phase B: Ps (34816B) overlays Q region; 3 K-stages of 18432 {Kh 0, Kl 9216}
#define AT_ROWB   144
#define PS_STRIDE 68
#define PA_STAGE  36864
#define PB_STAGE  18432
#define AT_SMEM   110592

__device__ __forceinline__ void kv_fill(uint32_t stb,
    const __nv_bfloat16* __restrict__ KhG, const __nv_bfloat16* __restrict__ KlG,
    const __nv_bfloat16* __restrict__ VhG, const __nv_bfloat16* __restrict__ VlG,
    int k0, int tid)
{
    const int r = tid >> 3, u = tid & 7;
    const uint32_t du = (uint32_t)(u * 16);
    const size_t so = (size_t)k0 * 1024 + u * 8;
    CP_A16(stb +     0u + (uint32_t)(r * 144)        + du, KhG + so + (size_t)r * 1024);
    CP_A16(stb +     0u + (uint32_t)((r + 32) * 144) + du, KhG + so + (size_t)(r + 32) * 1024);
    CP_A16(stb +  9216u + (uint32_t)(r * 144)        + du, KlG + so + (size_t)r * 1024);
    CP_A16(stb +  9216u + (uint32_t)((r + 32) * 144) + du, KlG + so + (size_t)(r + 32) * 1024);
    CP_A16(stb + 18432u + (uint32_t)(r * 144)        + du, VhG + so + (size_t)r * 1024);
    CP_A16(stb + 18432u + (uint32_t)((r + 32) * 144) + du, VhG + so + (size_t)(r + 32) * 1024);
    CP_A16(stb + 27648u + (uint32_t)(r * 144)        + du, VlG + so + (size_t)r * 1024);
    CP_A16(stb + 27648u + (uint32_t)((r + 32) * 144) + du, VlG + so + (size_t)(r + 32) * 1024);
}

__device__ __forceinline__ void k_fill(uint32_t stb,
    const __nv_bfloat16* __restrict__ KhG, const __nv_bfloat16* __restrict__ KlG,
    int k0, int tid)
{
    const int r = tid >> 3, u = tid & 7;
    const uint32_t du = (uint32_t)(u * 16);
    const size_t so = (size_t)k0 * 1024 + u * 8;
    CP_A16(stb +    0u + (uint32_t)(r * 144)        + du, KhG + so + (size_t)r * 1024);
    CP_A16(stb +    0u + (uint32_t)((r + 32) * 144) + du, KhG + so + (size_t)(r + 32) * 1024);
    CP_A16(stb + 9216u + (uint32_t)(r * 144)        + du, KlG + so + (size_t)r * 1024);
    CP_A16(stb + 9216u + (uint32_t)((r + 32) * 144) + du, KlG + so + (size_t)(r + 32) * 1024);
}

__global__ __launch_bounds__(256, 2)
void attn_fused(float* __restrict__ attn_out /* may be null */)
{
    extern __shared__ char sma[];
    __nv_bfloat16 (*Qh)[72] = (__nv_bfloat16(*)[72])(sma);
    __nv_bfloat16 (*Ql)[72] = (__nv_bfloat16(*)[72])(sma + 18432);
    float* Ps = (float*)sma;

    const int b  = blockIdx.z, h = blockIdx.y;
    const int q0 = blockIdx.x * 128;
    const int tid = threadIdx.x;
    const int w   = tid >> 5;
    const int l   = tid & 31;
    const int lr  = l >> 2;
    const int lc  = (l & 3) * 2;

    const int g   = l >> 3;
    const int rIn = l & 7;
    const uint32_t smb = smem_u32(sma);
    const uint32_t laneK_off  = (g < 2 ? 0u : 9216u) + (uint32_t)(rIn * AT_ROWB + (g & 1) * 16);
    const uint32_t laneVt_off = 18432u + (g < 2 ? 0u : 9216u) + (uint32_t)(((g & 1) * 8 + rIn) * AT_ROWB);

    const size_t base = ((size_t)b * Sv) * Ev + (size_t)h * 64;
    const __nv_bfloat16* QhG = g_Qbh + base;
    const __nv_bfloat16* QlG = g_Qbl + base;
    const __nv_bfloat16* KhG = g_Kbh + base;
    const __nv_bfloat16* KlG = g_Kbl + base;
    const __nv_bfloat16* VhG = g_Vbh + base;
    const __nv_bfloat16* VlG = g_Vbl + base;
    float* arow = attn_out ? attn_out + (((size_t)(b * Hv + h)) * Sv + q0) * Sv : (float*)0;

    kv_fill(smb + 36864u, KhG, KlG, VhG, VlG, 0, tid);
    CP_COMMIT();

    #pragma unroll
    for (int it = 0; it < 4; ++it) {
        int j = tid + it * 256;
        int r = j >> 3, u = j & 7;
        size_t go = (size_t)(q0 + r) * Ev + u * 8;
        *(uint4*)&Qh[r][u * 8] = *(const uint4*)(QhG + go);
        *(uint4*)&Ql[r][u * 8] = *(const uint4*)(QlG + go);
    }
    __syncthreads();

    uint32_t qh[4][4], ql[4][4];
    {
        const int r1 = w * 16 + lr;
        #pragma unroll
        for (int s = 0; s < 4; ++s) {
            int kb = s * 16 + lc;
            qh[s][0] = *(const uint32_t*)&Qh[r1    ][kb];
            qh[s][1] = *(const uint32_t*)&Qh[r1 + 8][kb];
            qh[s][2] = *(const uint32_t*)&Qh[r1    ][kb + 8];
            qh[s][3] = *(const uint32_t*)&Qh[r1 + 8][kb + 8];
            ql[s][0] = *(const uint32_t*)&Ql[r1    ][kb];
            ql[s][1] = *(const uint32_t*)&Ql[r1 + 8][kb];
            ql[s][2] = *(const uint32_t*)&Ql[r1    ][kb + 8];
            ql[s][3] = *(const uint32_t*)&Ql[r1 + 8][kb + 8];
        }
    }

    float oacc[8][4] = {};
    float sum0 = 0.f, sum1 = 0.f;

    // ════ PHASE A: S + exp + rowsums + unnormalized PV ════
    for (int c = 0; c < 32; ++c) {
        const int p = c & 1;
        if (c + 1 < 32) {
            kv_fill(smb + 36864u + (uint32_t)((1 - p) * PA_STAGE), KhG, KlG, VhG, VlG, (c + 1) * 64, tid);
            CP_COMMIT();
            CP_WAIT1();
        } else {
            CP_WAIT0();
        }
        __syncthreads();

        const uint32_t stb = smb + 36864u + (uint32_t)(p * PA_STAGE);
        const uint32_t laneK  = stb + laneK_off;
        const uint32_t laneVt = stb + laneVt_off;

        #pragma unroll
        for (int s = 0; s < 4; ++s) {
            float sa[2][4] = {};
            #pragma unroll
            for (int t = 0; t < 2; ++t) {
                const uint32_t ntoff = (uint32_t)((2 * s + t) * 8 * AT_ROWB);
                #pragma unroll
                for (int ks = 0; ks < 4; ++ks) {
                    uint32_t bh0, bh1, bl0, bl1;
                    LDSM_X4(bh0, bh1, bl0, bl1, laneK + ntoff + ks * 32);
                    MMA_BF16(sa[t], qh[ks][0], qh[ks][1], qh[ks][2], qh[ks][3], bh0, bh1);
                    MMA_BF16(sa[t], qh[ks][0], qh[ks][1], qh[ks][2], qh[ks][3], bl0, bl1);
                    MMA_BF16(sa[t], ql[ks][0], ql[ks][1], ql[ks][2], ql[ks][3], bh0, bh1);
                }
            }
            float p_[2][4];
            #pragma unroll
            for (int t = 0; t < 2; ++t) {
                #pragma unroll
                for (int cc = 0; cc < 4; ++cc) p_[t][cc] = __expf(sa[t][cc] * 0.125f);
                sum0 += p_[t][0] + p_[t][1];
                sum1 += p_[t][2] + p_[t][3];
            }
            uint32_t aPh[4], aPl[4];
            aPh[0] = pack2f(p_[0][0], p_[0][1], aPl[0]);
            aPh[1] = pack2f(p_[0][2], p_[0][3], aPl[1]);
            aPh[2] = pack2f(p_[1][0], p_[1][1], aPl[2]);
            aPh[3] = pack2f(p_[1][2], p_[1][3], aPl[3]);

            #pragma unroll
            for (int nt = 0; nt < 8; ++nt) {
                uint32_t vh0, vh1, vl0, vl1;
                LDSM_X4_T(vh0, vh1, vl0, vl1, laneVt + (uint32_t)(s * 16 * AT_ROWB + nt * 16));
                MMA_BF16(oacc[nt], aPh[0], aPh[1], aPh[2], aPh[3], vh0, vh1);
                MMA_BF16(oacc[nt], aPh[0], aPh[1], aPh[2], aPh[3], vl0, vl1);
                MMA_BF16(oacc[nt], aPl[0], aPl[1], aPl[2], aPl[3], vh0, vh1);
            }
        }
        __syncthreads();
    }

    // prefetch phase-B K stages 0,1 (hide under reduction/epilogue)
    if (arow) {
        k_fill(smb + 36864u, KhG, KlG, 0, tid);
        CP_COMMIT();
        k_fill(smb + 36864u + PB_STAGE, KhG, KlG, 64, tid);
        CP_COMMIT();
    }

    sum0 += __shfl_xor_sync(0xffffffffu, sum0, 1);
    sum0 += __shfl_xor_sync(0xffffffffu, sum0, 2);
    sum1 += __shfl_xor_sync(0xffffffffu, sum1, 1);
    sum1 += __shfl_xor_sync(0xffffffffu, sum1, 2);
    const float inv0 = 1.0f / sum0;
    const float inv1 = 1.0f / sum1;

    // normalized O -> hi/lo planes [B,S,E]
    {
        const int gr = b * Sv + q0 + w * 16 + lr;
        #pragma unroll
        for (int nt = 0; nt < 8; ++nt) {
            const int gc = h * 64 + nt * 8 + lc;
            uint32_t lo0, lo1;
            uint32_t hi0 = pack2f(oacc[nt][0] * inv0, oacc[nt][1] * inv0, lo0);
            uint32_t hi1 = pack2f(oacc[nt][2] * inv1, oacc[nt][3] * inv1, lo1);
            *(uint32_t*)&g_Obh[(size_t)gr * Ev + gc]       = hi0;
            *(uint32_t*)&g_Obl[(size_t)gr * Ev + gc]       = lo0;
            *(uint32_t*)&g_Obh[(size_t)(gr + 8) * Ev + gc] = hi1;
            *(uint32_t*)&g_Obl[(size_t)(gr + 8) * Ev + gc] = lo1;
        }
    }

    if (!arow) return;

    // ════ PHASE B: recompute S (bit-identical), normalize in-register, write P ════
    __syncthreads();   // all threads done with Q smem before Ps overlays

    for (int c = 0; c < 32; ++c) {
        const int p = c % 3;
        if (c + 2 < 32) {
            k_fill(smb + 36864u + (uint32_t)(((c + 2) % 3) * PB_STAGE), KhG, KlG, (c + 2) * 64, tid);
            CP_COMMIT();
            CP_WAIT2();
        } else if (c + 1 < 32) {
            CP_WAIT1();
        } else {
            CP_WAIT0();
        }
        __syncthreads();

        const uint32_t laneK = smb + 36864u + (uint32_t)(p * PB_STAGE) + laneK_off;
        const int k0 = c * 64;

        #pragma unroll
        for (int s = 0; s < 4; ++s) {
            float sa[2][4] = {};
            #pragma unroll
            for (int t = 0; t < 2; ++t) {
                const uint32_t ntoff = (uint32_t)((2 * s + t) * 8 * AT_ROWB);
                #pragma unroll
                for (int ks = 0; ks < 4; ++ks) {
                    uint32_t bh0, bh1, bl0, bl1;
                    LDSM_X4(bh0, bh1, bl0, bl1, laneK + ntoff + ks * 32);
                    MMA_BF16(sa[t], qh[ks][0], qh[ks][1], qh[ks][2], qh[ks][3], bh0, bh1);
                    MMA_BF16(sa[t], qh[ks][0], qh[ks][1], qh[ks][2], qh[ks][3], bl0, bl1);
                    MMA_BF16(sa[t], ql[ks][0], ql[ks][1], ql[ks][2], ql[ks][3], bh0, bh1);
                }
            }
            const int rbase = w * 16 + lr;
            const int cb = 16 * s + lc;
            #pragma unroll
            for (int t = 0; t < 2; ++t) {
                float p0 = __expf(sa[t][0] * 0.125f) * inv0;
                float p1 = __expf(sa[t][1] * 0.125f) * inv0;
                float p2 = __expf(sa[t][2] * 0.125f) * inv1;
                float p3 = __expf(sa[t][3] * 0.125f) * inv1;
                *(float2*)&Ps[(rbase    ) * PS_STRIDE + cb + 8*t] = make_float2(p0, p1);
                *(float2*)&Ps[(rbase + 8) * PS_STRIDE + cb + 8*t] = make_float2(p2, p3);
            }
        }

        __syncwarp();
        const int half = l >> 4;
        const int cc   = (l & 15) * 4;
        #pragma unroll
        for (int i = 0; i < 8; ++i) {
            const int r = w * 16 + i * 2 + half;
            *(float4*)(arow + (size_t)r * Sv + k0 + cc) = *(const float4*)&Ps[r * PS_STRIDE + cc];
        }
        __syncthreads();
    }
}

extern "C" void kernel_launch(void* const* d_in, const int* in_sizes, int n_in,
                              void* d_out, int out_size)
{
    const float* q  = (const float*)d_in[0];
    const float* k  = (const float*)d_in[1];
    const float* v  = (const float*)d_in[2];
    const float* Wq = (const float*)d_in[3];
    const float* Wk = (const float*)d_in[4];
    const float* Wv = (const float*)d_in[5];
    const float* Wo = (const float*)d_in[6];
    const float* bq = (const float*)d_in[7];
    const float* bk = (const float*)d_in[8];
    const float* bv = (const float*)d_in[9];
    const float* bo = (const float*)d_in[10];

    const long long BSE = (long long)Bv * Sv * Ev;                  // 8388608
    const long long ATT = (long long)Bv * Hv * Sv * (long long)Sv;  // 268435456
    float* out_ptr  = (float*)0;
    float* attn_ptr = (float*)0;
    long long osz = (long long)out_size;
    if (osz >= BSE + ATT)      { out_ptr = (float*)d_out; attn_ptr = (float*)d_out + BSE; }
    else if (osz >= ATT)       { attn_ptr = (float*)d_out; }
    else                       { out_ptr = (float*)d_out; }

    static int inited = 0;
    if (!inited) {
        cudaFuncSetAttribute(gemm_qkv,   cudaFuncAttributeMaxDynamicSharedMemorySize, G_SMEM);
        cudaFuncSetAttribute(gemm_o,     cudaFuncAttributeMaxDynamicSharedMemorySize, G_SMEM);
        cudaFuncSetAttribute(attn_fused, cudaFuncAttributeMaxDynamicSharedMemorySize, AT_SMEM);
        inited = 1;
    }

    conv_in<<<dim3(BSEn / 1024, 3), 256>>>(q, k, v);
    conv_w <<<dim3(Ev * Ev / 1024, 4), 256>>>(Wq, Wk, Wv, Wo);

    gemm_qkv<<<dim3(8, 64, 3), 256, G_SMEM>>>(bq, bk, bv);

    dim3 ag(Sv / 128, Hv, Bv);
    attn_fused<<<ag, 256, AT_SMEM>>>(attn_ptr);

    if (out_ptr) gemm_o<<<dim3(8, 64), 256, G_SMEM>>>(bo, out_ptr);
}